// round 15
// baseline (speedup 1.0000x reference)
#include <cuda_runtime.h>
#include <cuda_fp16.h>

#define HW 4096          // tokens
#define NH 8             // heads
#define CHUNK 512        // keys per attn block
#define CPAD 260         // padded uint stride for V^T rows (CHUNK/2 + 4)
#define KS 8             // key split for attention (partials add exactly)
#define FPIX 32          // pixels per finish block

// ---- scratch (device globals; no allocation allowed) ----
__device__ __align__(16) __half g_qh[NH * HW * 8];    // [h][n][8] f16, L2-norm * T*log2e
__device__ __align__(16) __half g_kh[NH * HW * 8];    // [h][m][8] f16, L2-norm
__device__ __align__(16) __half g_vt[NH * 8 * HW];    // [h][d][m] f16 (V transposed)
__device__ __align__(16) float g_pacct[KS * HW * 64]; // partial numerators [s][p][c] (transposed)
__device__ __align__(16) float g_pden[KS * NH * HW];  // partial denominators [s][h][p]

// ---- async copy helpers ----
__device__ __forceinline__ void cp16(void* dst, const void* src) {
    unsigned daddr = (unsigned)__cvta_generic_to_shared(dst);
    asm volatile("cp.async.cg.shared.global [%0], [%1], 16;" :: "r"(daddr), "l"(src) : "memory");
}
#define CP_COMMIT() asm volatile("cp.async.commit_group;" ::: "memory")
#define CP_WAIT(n)  asm volatile("cp.async.wait_group %0;" :: "n"(n) : "memory")

// pack two f32 -> f16x2
__device__ __forceinline__ unsigned packh2(float lo, float hi) {
    unsigned r; asm("cvt.rn.f16x2.f32 %0,%1,%2;" : "=r"(r) : "f"(hi), "f"(lo)); return r;
}
// packed half2 exp2
__device__ __forceinline__ unsigned ex2h2(unsigned x) {
    unsigned r; asm("ex2.approx.f16x2 %0,%1;" : "=r"(r) : "r"(x)); return r;
}
// S-mma: m16n8k8 f16 inputs, f32 accumulate, scalar C broadcast (bias)
__device__ __forceinline__ void mma_s(float& d0, float& d1, float& d2, float& d3,
                                      unsigned a0, unsigned a1, unsigned b0,
                                      float c) {
    asm("mma.sync.aligned.m16n8k8.row.col.f32.f16.f16.f32 "
        "{%0,%1,%2,%3},{%4,%5},{%6},{%7,%7,%7,%7};"
        : "=f"(d0), "=f"(d1), "=f"(d2), "=f"(d3)
        : "r"(a0), "r"(a1), "r"(b0), "f"(c));
}
// m16n8k16 f16 mma, accumulates in place
__device__ __forceinline__ void mma16(float& d0, float& d1, float& d2, float& d3,
                                      unsigned a0, unsigned a1, unsigned a2, unsigned a3,
                                      unsigned b0, unsigned b1) {
    asm("mma.sync.aligned.m16n8k16.row.col.f32.f16.f16.f32 "
        "{%0,%1,%2,%3},{%4,%5,%6,%7},{%8,%9},{%0,%1,%2,%3};"
        : "+f"(d0), "+f"(d1), "+f"(d2), "+f"(d3)
        : "r"(a0), "r"(a1), "r"(a2), "r"(a3), "r"(b0), "r"(b1));
}

// ============================================================================
// Kernel 1: q/k/v projection + per-head L2 norm; emit f16.
// TWO heads per task (halves redundant tile staging), input tile staged in
// smem via cp.async, 16 independent accumulators for ILP.
// grid = (32, 12), block = 128. task y: 0..3 q, 4..7 k, 8..11 v (head pairs).
// ============================================================================
__global__ __launch_bounds__(128)
void prep_kernel(const float* __restrict__ x, const float* __restrict__ y,
                 const float* __restrict__ wq, const float* __restrict__ wkv,
                 const float* __restrict__ temperature) {
    __shared__ __align__(16) float sIn[64 * 128];   // 32 KB
    __shared__ float sWT[64 * 16];                  // [c][16 rows], 4 KB
    const int tid   = threadIdx.x;
    const int pbase = blockIdx.x * 128;
    const int p     = pbase + tid;
    const int task  = blockIdx.y;
    const int typ   = task >> 2;      // 0=q, 1=k, 2=v
    const int h0    = (task & 3) * 2; // first head of the pair

    const float* wrow;
    if (typ == 0)      wrow = wq  + (h0 * 8) * 64;
    else if (typ == 1) wrow = wkv + (h0 * 8) * 64;
    else               wrow = wkv + (64 + h0 * 8) * 64;
#pragma unroll
    for (int i = tid; i < 1024; i += 128) {
        const int d = i >> 6, c = i & 63;
        sWT[c * 16 + d] = wrow[i];
    }

    const float* __restrict__ src = (typ == 0) ? x : y;
#pragma unroll
    for (int i = tid; i < 2048; i += 128) {
        const int c = i >> 5, j4 = i & 31;
        cp16(&((float4*)sIn)[i], (const float4*)(src + (size_t)c * HW + pbase) + j4);
    }
    CP_COMMIT(); CP_WAIT(0);
    __syncthreads();

    float acc[16];
#pragma unroll
    for (int d = 0; d < 16; d++) acc[d] = 0.f;

#pragma unroll
    for (int c = 0; c < 64; c++) {
        const float xv = sIn[c * 128 + tid];          // conflict-free LDS
#pragma unroll
        for (int k = 0; k < 4; k++) {
            const float4 w = *(const float4*)&sWT[c * 16 + 4 * k];   // broadcast
            acc[4*k+0] += w.x * xv; acc[4*k+1] += w.y * xv;
            acc[4*k+2] += w.z * xv; acc[4*k+3] += w.w * xv;
        }
    }

    if (typ == 2) {
#pragma unroll
        for (int d = 0; d < 16; d++)
            g_vt[((size_t)h0 * 8 + d) * HW + p] = __float2half_rn(acc[d]);
        return;
    }

    uint4* dst = (typ == 0) ? (uint4*)g_qh : (uint4*)g_kh;
#pragma unroll
    for (int hh = 0; hh < 2; hh++) {
        const int h = h0 + hh;
        float ss = 0.f;
#pragma unroll
        for (int d = 0; d < 8; d++) ss += acc[hh*8+d] * acc[hh*8+d];
        float scale = 1.f / fmaxf(sqrtf(ss), 1e-12f);
        if (typ == 0) scale *= temperature[h] * 1.4426950408889634f;

        __half2 a = __floats2half2_rn(acc[hh*8+0]*scale, acc[hh*8+1]*scale);
        __half2 b = __floats2half2_rn(acc[hh*8+2]*scale, acc[hh*8+3]*scale);
        __half2 c = __floats2half2_rn(acc[hh*8+4]*scale, acc[hh*8+5]*scale);
        __half2 d = __floats2half2_rn(acc[hh*8+6]*scale, acc[hh*8+7]*scale);
        uint4 row;
        row.x = *(unsigned*)&a; row.y = *(unsigned*)&b;
        row.z = *(unsigned*)&c; row.w = *(unsigned*)&d;
        dst[(size_t)h * HW + p] = row;
    }
}

// ============================================================================
// Kernel 2: flash attention on HMMA, key-split 8 ways.
// Block = 256 thr (8 warps); 128 queries of one head over ONE 512-key chunk.
// grid = (32, 8, 8) = 2048 blocks -> 8 blocks/SM (warp-limited), 100% occ.
// Constant-bias softmax => partials across key slices add exactly.
// Denominator via extra mma against ones (exact row-sum of the same f16 P).
// Epilogue writes transposed partials g_pacct[s][p][c].
// ============================================================================
__global__ __launch_bounds__(256)
void attn_kernel(const float* __restrict__ temperature) {
    __shared__ __align__(16) unsigned sK[CHUNK * 4];   // 8 KB
    __shared__ __align__(16) unsigned sVT[8 * CPAD];   // 8.3 KB

    const int h    = blockIdx.y;
    const int s    = blockIdx.z;                 // chunk index = key split
    const int tid  = threadIdx.x;
    const int wid  = tid >> 5;
    const int lane = tid & 31;
    const int r = lane >> 2, m = lane & 3;
    const int q0 = blockIdx.x * 128 + wid * 16;

    const float bias = -fabsf(temperature[h]) * 1.4426950408889634f;
    const unsigned ONES = 0x3C003C00u;

    const unsigned* qU = (const unsigned*)g_qh + (size_t)h * HW * 4;
    const unsigned a0q = qU[(q0 + r) * 4 + m];
    const unsigned a1q = qU[(q0 + r + 8) * 4 + m];

    const uint4*    gK4 = (const uint4*)((const unsigned*)g_kh + (size_t)h * HW * 4);
    const unsigned* gV  = (const unsigned*)g_vt + (size_t)h * 8 * (HW / 2);

    // stage this block's single chunk
#pragma unroll
    for (int i = tid; i < CHUNK; i += 256)
        cp16(&((uint4*)sK)[i], &gK4[s * CHUNK + i]);
#pragma unroll
    for (int i = tid; i < 512; i += 256) {
        const int row = i >> 6, c16 = i & 63;
        cp16((uint4*)(sVT + row * CPAD + c16 * 4),
             (const uint4*)(gV + row * (HW / 2) + s * (CHUNK / 2) + c16 * 4));
    }
    CP_COMMIT(); CP_WAIT(0);
    __syncthreads();

    float o0 = 0.f, o1 = 0.f, o2 = 0.f, o3 = 0.f;
    float dd0 = 0.f, dd1 = 0.f, dd2 = 0.f, dd3 = 0.f;

#pragma unroll 4
    for (int kb = 0; kb < CHUNK; kb += 16) {
        const unsigned kb0 = sK[(kb + r) * 4 + m];
        const unsigned kb1 = sK[(kb + 8 + r) * 4 + m];

        float s0, s1, s2, s3, t0, t1, t2, t3;
        mma_s(s0, s1, s2, s3, a0q, a1q, kb0, bias);
        mma_s(t0, t1, t2, t3, a0q, a1q, kb1, bias);

        const unsigned p0 = ex2h2(packh2(s0, s1));
        const unsigned p1 = ex2h2(packh2(s2, s3));
        const unsigned p2 = ex2h2(packh2(t0, t1));
        const unsigned p3 = ex2h2(packh2(t2, t3));

        const unsigned vb0 = sVT[r * CPAD + (kb >> 1) + m];
        const unsigned vb1 = sVT[r * CPAD + (kb >> 1) + m + 4];
        mma16(o0, o1, o2, o3, p0, p1, p2, p3, vb0, vb1);
        mma16(dd0, dd1, dd2, dd3, p0, p1, p2, p3, ONES, ONES);
    }

    // transposed partial writes: [s][p][c]
    float* pa = g_pacct + (size_t)s * (HW * 64);
    *(float2*)&pa[(size_t)(q0 + r    ) * 64 + h * 8 + 2 * m] = make_float2(o0, o1);
    *(float2*)&pa[(size_t)(q0 + r + 8) * 64 + h * 8 + 2 * m] = make_float2(o2, o3);
    if (m == 0) {   // dd0/dd2 identical across the quad (B = ones)
        float* pd = g_pden + ((size_t)s * NH + h) * HW;
        pd[q0 + r    ] = dd0;
        pd[q0 + r + 8] = dd2;
    }
}

// ============================================================================
// Kernel 3: fused reduce + output projection on HMMA.
// Block = 256 thr (8 warps), FPIX=32 pixels; grid = 128.
// Sum KS split-partials, multiply by 1/den, cvt f16 -> sB[p][c]; W -> f16.
// out[64 x 32] = W(64x64) @ B(64x32) via m16n8k16, f32 accumulate.
// ============================================================================
__global__ __launch_bounds__(256)
void finish_kernel(const float* __restrict__ wout, float* __restrict__ out) {
    __shared__ unsigned sW[64 * 36];     // f16 pairs [o][36], 9 KB
    __shared__ unsigned sB[FPIX * 36];   // f16 pairs [p][36], 4.5 KB
    __shared__ float sRden[NH * FPIX];   // 1 KB
    const int tid   = threadIdx.x;
    const int pbase = blockIdx.x * FPIX;

#pragma unroll
    for (int i = tid; i < 64 * 32; i += 256) {
        const int o = i >> 5, cp = i & 31;
        const float2 w = *(const float2*)&wout[o * 64 + cp * 2];
        sW[o * 36 + cp] = packh2(w.x, w.y);
    }

    if (tid < NH * (FPIX / 4)) {
        const int h = tid >> 3, g = tid & 7;
        float4 d = make_float4(0.f, 0.f, 0.f, 0.f);
#pragma unroll
        for (int s = 0; s < KS; s++) {
            const float4 v = *(const float4*)&g_pden[((size_t)s * NH + h) * HW + pbase + g * 4];
            d.x += v.x; d.y += v.y; d.z += v.z; d.w += v.w;
        }
        *(float4*)&sRden[h * FPIX + g * 4] =
            make_float4(1.f / d.x, 1.f / d.y, 1.f / d.z, 1.f / d.w);
    }
    __syncthreads();

#pragma unroll
    for (int i = tid; i < FPIX * 16; i += 256) {
        const int p = i >> 4, cg = i & 15;
        float4 a = make_float4(0.f, 0.f, 0.f, 0.f);
#pragma unroll
        for (int s = 0; s < KS; s++) {
            const float4 v = *(const float4*)
                &g_pacct[(size_t)s * (HW * 64) + (size_t)(pbase + p) * 64 + cg * 4];
            a.x += v.x; a.y += v.y; a.z += v.z; a.w += v.w;
        }
        const float rd = sRden[(cg >> 1) * FPIX + p];
        sB[p * 36 + cg * 2]     = packh2(a.x * rd, a.y * rd);
        sB[p * 36 + cg * 2 + 1] = packh2(a.z * rd, a.w * rd);
    }
    __syncthreads();

    const int w    = tid >> 5;
    const int lane = tid & 31;
    const int r = lane >> 2, m4 = lane & 3;
    const int mrow = (w & 3) * 16;
    const int nt0  = (w >> 2) * 2;

    unsigned A[4][4];
#pragma unroll
    for (int k = 0; k < 4; k++) {
        A[k][0] = sW[(mrow + r    ) * 36 + 8 * k + m4];
        A[k][1] = sW[(mrow + r + 8) * 36 + 8 * k + m4];
        A[k][2] = sW[(mrow + r    ) * 36 + 8 * k + m4 + 4];
        A[k][3] = sW[(mrow + r + 8) * 36 + 8 * k + m4 + 4];
    }

#pragma unroll
    for (int nt = nt0; nt < nt0 + 2; nt++) {
        float d0 = 0.f, d1 = 0.f, d2 = 0.f, d3 = 0.f;
#pragma unroll
        for (int k = 0; k < 4; k++) {
            const unsigned b0 = sB[(nt * 8 + r) * 36 + 8 * k + m4];
            const unsigned b1 = sB[(nt * 8 + r) * 36 + 8 * k + m4 + 4];
            mma16(d0, d1, d2, d3, A[k][0], A[k][1], A[k][2], A[k][3], b0, b1);
        }
        const int pcol = pbase + nt * 8 + 2 * m4;
        *(float2*)&out[(size_t)(mrow + r    ) * HW + pcol] = make_float2(d0, d1);
        *(float2*)&out[(size_t)(mrow + r + 8) * HW + pcol] = make_float2(d2, d3);
    }
}

// ============================================================================
extern "C" void kernel_launch(void* const* d_in, const int* in_sizes, int n_in,
                              void* d_out, int out_size) {
    const float* x    = (const float*)d_in[0];
    const float* y    = (const float*)d_in[1];
    const float* wq   = (const float*)d_in[2];
    const float* wkv  = (const float*)d_in[3];
    const float* wout = (const float*)d_in[4];
    const float* temp = (const float*)d_in[5];
    float* out = (float*)d_out;

    prep_kernel<<<dim3(32, 12), 128>>>(x, y, wq, wkv, temp);
    attn_kernel<<<dim3(32, 8, KS), 256>>>(temp);
    finish_kernel<<<128, 256>>>(wout, out);
}

// round 16
// speedup vs baseline: 1.5553x; 1.5553x over previous
#include <cuda_runtime.h>
#include <cuda_fp16.h>

#define HW 4096          // tokens
#define NH 8             // heads
#define CHUNK 512        // keys per smem stage
#define CPAD 260         // padded uint stride for V^T rows (CHUNK/2 + 4)
#define KS 4             // key split for attention (partials add exactly)
#define FPIX 32          // pixels per finish block

// ---- scratch (device globals; no allocation allowed) ----
__device__ __align__(16) __half g_qh[NH * HW * 8];    // [h][n][8] f16, L2-norm * T*log2e
__device__ __align__(16) __half g_kh[NH * HW * 8];    // [h][m][8] f16, L2-norm
__device__ __align__(16) __half g_vt[NH * 8 * HW];    // [h][d][m] f16 (V transposed)
__device__ __align__(16) float g_pacct[KS * HW * 64]; // partial numerators [s][p][c] (transposed)
__device__ __align__(16) float g_pden[KS * NH * HW];  // partial denominators [s][h][p]

// ---- async copy helpers ----
__device__ __forceinline__ void cp16(void* dst, const void* src) {
    unsigned daddr = (unsigned)__cvta_generic_to_shared(dst);
    asm volatile("cp.async.cg.shared.global [%0], [%1], 16;" :: "r"(daddr), "l"(src) : "memory");
}
#define CP_COMMIT() asm volatile("cp.async.commit_group;" ::: "memory")
#define CP_WAIT(n)  asm volatile("cp.async.wait_group %0;" :: "n"(n) : "memory")

// pack two f32 -> f16x2
__device__ __forceinline__ unsigned packh2(float lo, float hi) {
    unsigned r; asm("cvt.rn.f16x2.f32 %0,%1,%2;" : "=r"(r) : "f"(hi), "f"(lo)); return r;
}
// packed half2 exp2
__device__ __forceinline__ unsigned ex2h2(unsigned x) {
    unsigned r; asm("ex2.approx.f16x2 %0,%1;" : "=r"(r) : "r"(x)); return r;
}
// S-mma: m16n8k8 f16 inputs, f32 accumulate, scalar C broadcast (bias)
__device__ __forceinline__ void mma_s(float& d0, float& d1, float& d2, float& d3,
                                      unsigned a0, unsigned a1, unsigned b0,
                                      float c) {
    asm("mma.sync.aligned.m16n8k8.row.col.f32.f16.f16.f32 "
        "{%0,%1,%2,%3},{%4,%5},{%6},{%7,%7,%7,%7};"
        : "=f"(d0), "=f"(d1), "=f"(d2), "=f"(d3)
        : "r"(a0), "r"(a1), "r"(b0), "f"(c));
}
// m16n8k16 f16 mma, accumulates in place
__device__ __forceinline__ void mma16(float& d0, float& d1, float& d2, float& d3,
                                      unsigned a0, unsigned a1, unsigned a2, unsigned a3,
                                      unsigned b0, unsigned b1) {
    asm("mma.sync.aligned.m16n8k16.row.col.f32.f16.f16.f32 "
        "{%0,%1,%2,%3},{%4,%5,%6,%7},{%8,%9},{%0,%1,%2,%3};"
        : "+f"(d0), "+f"(d1), "+f"(d2), "+f"(d3)
        : "r"(a0), "r"(a1), "r"(a2), "r"(a3), "r"(b0), "r"(b1));
}

// ============================================================================
// Kernel 1: q/k/v projection + per-head L2 norm; emit f16.
// 128-pixel tile staged in smem via cp.async; conflict-free LDS.
// grid = (32, 24), block = 128.  (single-head tasks: block count wins)
// ============================================================================
__global__ __launch_bounds__(128)
void prep_kernel(const float* __restrict__ x, const float* __restrict__ y,
                 const float* __restrict__ wq, const float* __restrict__ wkv,
                 const float* __restrict__ temperature) {
    __shared__ __align__(16) float sIn[64 * 128];   // 32 KB
    __shared__ float sWT[64 * 8];                   // 2 KB
    const int tid   = threadIdx.x;
    const int pbase = blockIdx.x * 128;
    const int p     = pbase + tid;
    const int task  = blockIdx.y;
    const int typ   = task >> 3;      // 0=q, 1=k, 2=v
    const int h     = task & 7;

    const float* wrow;
    if (typ == 0)      wrow = wq  + (h * 8) * 64;
    else if (typ == 1) wrow = wkv + (h * 8) * 64;
    else               wrow = wkv + (64 + h * 8) * 64;
#pragma unroll
    for (int i = tid; i < 512; i += 128) {
        const int d = i >> 6, c = i & 63;
        sWT[c * 8 + d] = wrow[i];
    }

    const float* __restrict__ src = (typ == 0) ? x : y;
#pragma unroll
    for (int i = tid; i < 2048; i += 128) {
        const int c = i >> 5, j4 = i & 31;
        cp16(&((float4*)sIn)[i], (const float4*)(src + (size_t)c * HW + pbase) + j4);
    }
    CP_COMMIT(); CP_WAIT(0);
    __syncthreads();

    float acc[8];
#pragma unroll
    for (int d = 0; d < 8; d++) acc[d] = 0.f;

#pragma unroll
    for (int c = 0; c < 64; c++) {
        const float xv = sIn[c * 128 + tid];
        const float4 w0 = *(const float4*)&sWT[c * 8];
        const float4 w1 = *(const float4*)&sWT[c * 8 + 4];
        acc[0] += w0.x * xv; acc[1] += w0.y * xv;
        acc[2] += w0.z * xv; acc[3] += w0.w * xv;
        acc[4] += w1.x * xv; acc[5] += w1.y * xv;
        acc[6] += w1.z * xv; acc[7] += w1.w * xv;
    }

    if (typ == 2) {
#pragma unroll
        for (int d = 0; d < 8; d++)
            g_vt[((size_t)h * 8 + d) * HW + p] = __float2half_rn(acc[d]);
        return;
    }

    float ss = 0.f;
#pragma unroll
    for (int d = 0; d < 8; d++) ss += acc[d] * acc[d];
    float scale = 1.f / fmaxf(sqrtf(ss), 1e-12f);
    if (typ == 0) scale *= temperature[h] * 1.4426950408889634f;

    __half2 h01 = __floats2half2_rn(acc[0] * scale, acc[1] * scale);
    __half2 h23 = __floats2half2_rn(acc[2] * scale, acc[3] * scale);
    __half2 h45 = __floats2half2_rn(acc[4] * scale, acc[5] * scale);
    __half2 h67 = __floats2half2_rn(acc[6] * scale, acc[7] * scale);
    uint4 row;
    row.x = *(unsigned*)&h01; row.y = *(unsigned*)&h23;
    row.z = *(unsigned*)&h45; row.w = *(unsigned*)&h67;
    uint4* dst = (typ == 0) ? (uint4*)g_qh : (uint4*)g_kh;
    dst[(size_t)h * HW + p] = row;
}

// ============================================================================
// Kernel 2: flash attention on HMMA, key-split 4 ways, cp.async double-buffer.
// __launch_bounds__(256, 4): cap at 64 regs -> 4 resident blocks/SM
// (32 warps) instead of the register-limited 3. Block = 256 thr (8 warps);
// 128 queries of one head over 1024 keys (2 chunks, both staged up front).
// grid = (32, 8, 4). Constant-bias softmax => partials add exactly.
// ============================================================================
__global__ __launch_bounds__(256, 4)
void attn_kernel(const float* __restrict__ temperature) {
    __shared__ __align__(16) unsigned sK[2][CHUNK * 4];   // 8 KB each
    __shared__ __align__(16) unsigned sVT[2][8 * CPAD];   // 8.3 KB each

    const int h    = blockIdx.y;
    const int s    = blockIdx.z;
    const int tid  = threadIdx.x;
    const int wid  = tid >> 5;
    const int lane = tid & 31;
    const int r = lane >> 2, m = lane & 3;
    const int q0 = blockIdx.x * 128 + wid * 16;

    const float bias = -fabsf(temperature[h]) * 1.4426950408889634f;
    const unsigned ONES = 0x3C003C00u;

    const unsigned* qU = (const unsigned*)g_qh + (size_t)h * HW * 4;
    const unsigned a0q = qU[(q0 + r) * 4 + m];
    const unsigned a1q = qU[(q0 + r + 8) * 4 + m];

    float o0 = 0.f, o1 = 0.f, o2 = 0.f, o3 = 0.f;
    float dd0 = 0.f, dd1 = 0.f, dd2 = 0.f, dd3 = 0.f;

    const uint4*    gK4 = (const uint4*)((const unsigned*)g_kh + (size_t)h * HW * 4);
    const unsigned* gV  = (const unsigned*)g_vt + (size_t)h * 8 * (HW / 2);

    const int ch0 = s * 2;     // 2 chunks of 512 per block

#pragma unroll
    for (int b = 0; b < 2; b++) {
        const int ch = ch0 + b;
#pragma unroll
        for (int i = tid; i < CHUNK; i += 256)
            cp16(&((uint4*)sK[b])[i], &gK4[ch * CHUNK + i]);
#pragma unroll
        for (int i = tid; i < 512; i += 256) {
            const int row = i >> 6, c16 = i & 63;
            cp16((uint4*)(sVT[b] + row * CPAD + c16 * 4),
                 (const uint4*)(gV + row * (HW / 2) + ch * (CHUNK / 2) + c16 * 4));
        }
        CP_COMMIT();
    }

#pragma unroll
    for (int b = 0; b < 2; b++) {
        if (b == 0) { CP_WAIT(1); } else { CP_WAIT(0); }
        __syncthreads();

        const unsigned* bK = sK[b];
        const unsigned* bV = sVT[b];
#pragma unroll 4
        for (int kb = 0; kb < CHUNK; kb += 16) {
            const unsigned kb0 = bK[(kb + r) * 4 + m];
            const unsigned kb1 = bK[(kb + 8 + r) * 4 + m];

            float s0, s1, s2, s3, t0, t1, t2, t3;
            mma_s(s0, s1, s2, s3, a0q, a1q, kb0, bias);
            mma_s(t0, t1, t2, t3, a0q, a1q, kb1, bias);

            const unsigned p0 = ex2h2(packh2(s0, s1));
            const unsigned p1 = ex2h2(packh2(s2, s3));
            const unsigned p2 = ex2h2(packh2(t0, t1));
            const unsigned p3 = ex2h2(packh2(t2, t3));

            const unsigned vb0 = bV[r * CPAD + (kb >> 1) + m];
            const unsigned vb1 = bV[r * CPAD + (kb >> 1) + m + 4];
            mma16(o0, o1, o2, o3, p0, p1, p2, p3, vb0, vb1);
            mma16(dd0, dd1, dd2, dd3, p0, p1, p2, p3, ONES, ONES);
        }
    }

    // transposed partial writes: [s][p][c]
    float* pa = g_pacct + (size_t)s * (HW * 64);
    *(float2*)&pa[(size_t)(q0 + r    ) * 64 + h * 8 + 2 * m] = make_float2(o0, o1);
    *(float2*)&pa[(size_t)(q0 + r + 8) * 64 + h * 8 + 2 * m] = make_float2(o2, o3);
    if (m == 0) {   // dd0/dd2 identical across the quad (B = ones)
        float* pd = g_pden + ((size_t)s * NH + h) * HW;
        pd[q0 + r    ] = dd0;
        pd[q0 + r + 8] = dd2;
    }
}

// ============================================================================
// Kernel 3: fused reduce + output projection on HMMA.
// Block = 256 thr (8 warps), FPIX=32 pixels; grid = 128.
// ============================================================================
__global__ __launch_bounds__(256)
void finish_kernel(const float* __restrict__ wout, float* __restrict__ out) {
    __shared__ unsigned sW[64 * 36];     // f16 pairs [o][36], 9 KB
    __shared__ unsigned sB[FPIX * 36];   // f16 pairs [p][36], 4.5 KB
    __shared__ float sRden[NH * FPIX];   // 1 KB
    const int tid   = threadIdx.x;
    const int pbase = blockIdx.x * FPIX;

#pragma unroll
    for (int i = tid; i < 64 * 32; i += 256) {
        const int o = i >> 5, cp = i & 31;
        const float2 w = *(const float2*)&wout[o * 64 + cp * 2];
        sW[o * 36 + cp] = packh2(w.x, w.y);
    }

    if (tid < NH * (FPIX / 4)) {
        const int h = tid >> 3, g = tid & 7;
        float4 d = make_float4(0.f, 0.f, 0.f, 0.f);
#pragma unroll
        for (int s = 0; s < KS; s++) {
            const float4 v = *(const float4*)&g_pden[((size_t)s * NH + h) * HW + pbase + g * 4];
            d.x += v.x; d.y += v.y; d.z += v.z; d.w += v.w;
        }
        *(float4*)&sRden[h * FPIX + g * 4] =
            make_float4(1.f / d.x, 1.f / d.y, 1.f / d.z, 1.f / d.w);
    }
    __syncthreads();

#pragma unroll
    for (int i = tid; i < FPIX * 16; i += 256) {
        const int p = i >> 4, cg = i & 15;
        float4 a = make_float4(0.f, 0.f, 0.f, 0.f);
#pragma unroll
        for (int s = 0; s < KS; s++) {
            const float4 v = *(const float4*)
                &g_pacct[(size_t)s * (HW * 64) + (size_t)(pbase + p) * 64 + cg * 4];
            a.x += v.x; a.y += v.y; a.z += v.z; a.w += v.w;
        }
        const float rd = sRden[(cg >> 1) * FPIX + p];
        sB[p * 36 + cg * 2]     = packh2(a.x * rd, a.y * rd);
        sB[p * 36 + cg * 2 + 1] = packh2(a.z * rd, a.w * rd);
    }
    __syncthreads();

    const int w    = tid >> 5;
    const int lane = tid & 31;
    const int r = lane >> 2, m4 = lane & 3;
    const int mrow = (w & 3) * 16;
    const int nt0  = (w >> 2) * 2;

    unsigned A[4][4];
#pragma unroll
    for (int k = 0; k < 4; k++) {
        A[k][0] = sW[(mrow + r    ) * 36 + 8 * k + m4];
        A[k][1] = sW[(mrow + r + 8) * 36 + 8 * k + m4];
        A[k][2] = sW[(mrow + r    ) * 36 + 8 * k + m4 + 4];
        A[k][3] = sW[(mrow + r + 8) * 36 + 8 * k + m4 + 4];
    }

#pragma unroll
    for (int nt = nt0; nt < nt0 + 2; nt++) {
        float d0 = 0.f, d1 = 0.f, d2 = 0.f, d3 = 0.f;
#pragma unroll
        for (int k = 0; k < 4; k++) {
            const unsigned b0 = sB[(nt * 8 + r) * 36 + 8 * k + m4];
            const unsigned b1 = sB[(nt * 8 + r) * 36 + 8 * k + m4 + 4];
            mma16(d0, d1, d2, d3, A[k][0], A[k][1], A[k][2], A[k][3], b0, b1);
        }
        const int pcol = pbase + nt * 8 + 2 * m4;
        *(float2*)&out[(size_t)(mrow + r    ) * HW + pcol] = make_float2(d0, d1);
        *(float2*)&out[(size_t)(mrow + r + 8) * HW + pcol] = make_float2(d2, d3);
    }
}

// ============================================================================
extern "C" void kernel_launch(void* const* d_in, const int* in_sizes, int n_in,
                              void* d_out, int out_size) {
    const float* x    = (const float*)d_in[0];
    const float* y    = (const float*)d_in[1];
    const float* wq   = (const float*)d_in[2];
    const float* wkv  = (const float*)d_in[3];
    const float* wout = (const float*)d_in[4];
    const float* temp = (const float*)d_in[5];
    float* out = (float*)d_out;

    prep_kernel<<<dim3(32, 24), 128>>>(x, y, wq, wkv, temp);
    attn_kernel<<<dim3(32, 8, KS), 256>>>(temp);
    finish_kernel<<<128, 256>>>(wout, out);
}

// round 17
// speedup vs baseline: 1.6455x; 1.0580x over previous
#include <cuda_runtime.h>
#include <cuda_fp16.h>

#define HW 4096          // tokens
#define NH 8             // heads
#define CHUNK 512        // keys per smem stage
#define CPAD 260         // padded uint stride for V^T rows (CHUNK/2 + 4)
#define KS 4             // key split for attention (partials add exactly)
#define FPIX 32          // pixels per finish block

// ---- scratch (device globals; no allocation allowed) ----
__device__ __align__(16) __half g_qh[NH * HW * 8];    // [h][n][8] f16, L2-norm * T*log2e
__device__ __align__(16) __half g_kh[NH * HW * 8];    // [h][m][8] f16, L2-norm
__device__ __align__(16) __half g_vt[NH * 8 * HW];    // [h][d][m] f16 (V transposed) == [c][p]
__device__ __align__(16) float g_pacct[KS * HW * 64]; // partial numerators [s][p][c] (transposed)
__device__ __align__(16) float g_pden[KS * NH * HW];  // partial denominators [s][h][p]

// ---- async copy helpers ----
__device__ __forceinline__ void cp16(void* dst, const void* src) {
    unsigned daddr = (unsigned)__cvta_generic_to_shared(dst);
    asm volatile("cp.async.cg.shared.global [%0], [%1], 16;" :: "r"(daddr), "l"(src) : "memory");
}
#define CP_COMMIT() asm volatile("cp.async.commit_group;" ::: "memory")
#define CP_WAIT(n)  asm volatile("cp.async.wait_group %0;" :: "n"(n) : "memory")

// pack two f32 -> f16x2
__device__ __forceinline__ unsigned packh2(float lo, float hi) {
    unsigned r; asm("cvt.rn.f16x2.f32 %0,%1,%2;" : "=r"(r) : "f"(hi), "f"(lo)); return r;
}
// packed half2 exp2
__device__ __forceinline__ unsigned ex2h2(unsigned x) {
    unsigned r; asm("ex2.approx.f16x2 %0,%1;" : "=r"(r) : "r"(x)); return r;
}
// S-mma: m16n8k8 f16 inputs, f32 accumulate, scalar C broadcast (bias)
__device__ __forceinline__ void mma_s(float& d0, float& d1, float& d2, float& d3,
                                      unsigned a0, unsigned a1, unsigned b0,
                                      float c) {
    asm("mma.sync.aligned.m16n8k8.row.col.f32.f16.f16.f32 "
        "{%0,%1,%2,%3},{%4,%5},{%6},{%7,%7,%7,%7};"
        : "=f"(d0), "=f"(d1), "=f"(d2), "=f"(d3)
        : "r"(a0), "r"(a1), "r"(b0), "f"(c));
}
// m16n8k16 f16 mma, accumulates in place
__device__ __forceinline__ void mma16(float& d0, float& d1, float& d2, float& d3,
                                      unsigned a0, unsigned a1, unsigned a2, unsigned a3,
                                      unsigned b0, unsigned b1) {
    asm("mma.sync.aligned.m16n8k16.row.col.f32.f16.f16.f32 "
        "{%0,%1,%2,%3},{%4,%5,%6,%7},{%8,%9},{%0,%1,%2,%3};"
        : "+f"(d0), "+f"(d1), "+f"(d2), "+f"(d3)
        : "r"(a0), "r"(a1), "r"(a2), "r"(a3), "r"(b0), "r"(b1));
}

// ============================================================================
// Kernel 1: q/k/v projection on HMMA + per-head L2 norm in the epilogue.
// grid = (64 pixel-tiles, 3 tasks), block = 256 (8 warps).
// Per block: one 64x64 @ 64x64 GEMM tile (W f16 x input f16, f32 accum).
// Norm: quad-column shfl_xor(4,8,16) gives exact per-(head,pixel) sum of
// squares; scale (q also by T*log2e), pack f16.
// q/k: assemble [p][8ch] rows in smem -> uint4 stores. v: direct half2 ([c][p]).
// ============================================================================
__global__ __launch_bounds__(256)
void prep_kernel(const float* __restrict__ x, const float* __restrict__ y,
                 const float* __restrict__ wq, const float* __restrict__ wkv,
                 const float* __restrict__ temperature) {
    __shared__ unsigned sA[64 * 36];     // W f16 pairs [o][cp], 9 KB
    __shared__ unsigned sB[64 * 36];     // input f16 pairs [p][cp], 9 KB
    __shared__ __half  sOut[64 * 64];    // [p][c], 8 KB
    const int tid   = threadIdx.x;
    const int pbase = blockIdx.x * 64;
    const int typ   = blockIdx.y;        // 0=q, 1=k, 2=v

    const float* wrow = (typ == 0) ? wq : (wkv + (typ == 2 ? 64 * 64 : 0));
#pragma unroll
    for (int i = tid; i < 64 * 32; i += 256) {
        const int o = i >> 5, cp = i & 31;
        const float2 w = *(const float2*)&wrow[o * 64 + cp * 2];
        sA[o * 36 + cp] = packh2(w.x, w.y);
    }

    // input tile [c][p] f32 -> [p][cpair] f16 (transpose during convert)
    const float* __restrict__ src = (typ == 0) ? x : y;
#pragma unroll
    for (int i = tid; i < 2048; i += 256) {
        const int p = i & 63, j = i >> 6;            // j = channel pair 0..31
        const float a = src[(size_t)(2 * j    ) * HW + pbase + p];
        const float b = src[(size_t)(2 * j + 1) * HW + pbase + p];
        sB[p * 36 + j] = packh2(a, b);
    }
    __syncthreads();

    const int w    = tid >> 5;
    const int lane = tid & 31;
    const int r = lane >> 2, m4 = lane & 3;
    const int mt   = w & 3;
    const int mrow = mt * 16;
    const int nt0  = (w >> 2) * 4;

    unsigned A[4][4];
#pragma unroll
    for (int k = 0; k < 4; k++) {
        A[k][0] = sA[(mrow + r    ) * 36 + 8 * k + m4];
        A[k][1] = sA[(mrow + r + 8) * 36 + 8 * k + m4];
        A[k][2] = sA[(mrow + r    ) * 36 + 8 * k + m4 + 4];
        A[k][3] = sA[(mrow + r + 8) * 36 + 8 * k + m4 + 4];
    }

    const float L2E = 1.4426950408889634f;
    // per-row scale multiplier: q -> T*log2e, k -> 1 (v skips norm entirely)
    const float tA = (typ == 0) ? temperature[mt * 2    ] * L2E : 1.f;
    const float tB = (typ == 0) ? temperature[mt * 2 + 1] * L2E : 1.f;

#pragma unroll
    for (int nt = nt0; nt < nt0 + 4; nt++) {
        float d0 = 0.f, d1 = 0.f, d2 = 0.f, d3 = 0.f;
#pragma unroll
        for (int k = 0; k < 4; k++) {
            const unsigned b0 = sB[(nt * 8 + r) * 36 + 8 * k + m4];
            const unsigned b1 = sB[(nt * 8 + r) * 36 + 8 * k + m4 + 4];
            mma16(d0, d1, d2, d3, A[k][0], A[k][1], A[k][2], A[k][3], b0, b1);
        }
        const int pl = nt * 8 + 2 * m4;   // local pixel of d0/d2 (d1/d3: pl+1)

        if (typ == 2) {
            // V: rows are channels, natural [c][p] layout -> direct half2
            *(unsigned*)&g_vt[(size_t)(mrow + r    ) * HW + pbase + pl] = packh2(d0, d1);
            *(unsigned*)&g_vt[(size_t)(mrow + r + 8) * HW + pbase + pl] = packh2(d2, d3);
        } else {
            // per-(head,pixel) sum of squares across the 8 channel-lanes
            float s0 = d0 * d0, s1 = d1 * d1, s2 = d2 * d2, s3 = d3 * d3;
#pragma unroll
            for (int mk = 4; mk <= 16; mk <<= 1) {
                s0 += __shfl_xor_sync(0xffffffffu, s0, mk);
                s1 += __shfl_xor_sync(0xffffffffu, s1, mk);
                s2 += __shfl_xor_sync(0xffffffffu, s2, mk);
                s3 += __shfl_xor_sync(0xffffffffu, s3, mk);
            }
            const float c0 = tA / fmaxf(sqrtf(s0), 1e-12f);
            const float c1 = tA / fmaxf(sqrtf(s1), 1e-12f);
            const float c2 = tB / fmaxf(sqrtf(s2), 1e-12f);
            const float c3 = tB / fmaxf(sqrtf(s3), 1e-12f);
            sOut[(pl    ) * 64 + mrow + r    ] = __float2half_rn(d0 * c0);
            sOut[(pl + 1) * 64 + mrow + r    ] = __float2half_rn(d1 * c1);
            sOut[(pl    ) * 64 + mrow + r + 8] = __float2half_rn(d2 * c2);
            sOut[(pl + 1) * 64 + mrow + r + 8] = __float2half_rn(d3 * c3);
        }
    }

    if (typ != 2) {
        __syncthreads();
        uint4* dst = (typ == 0) ? (uint4*)g_qh : (uint4*)g_kh;
#pragma unroll
        for (int i = tid; i < 512; i += 256) {
            const int p = i >> 3, h = i & 7;
            dst[(size_t)h * HW + pbase + p] = *(uint4*)&sOut[p * 64 + h * 8];
        }
    }
}

// ============================================================================
// Kernel 2: flash attention on HMMA, key-split 4 ways, cp.async double-buffer.
// Block = 256 thr (8 warps); 128 queries of one head over 1024 keys.
// grid = (32, 8, 4). Constant-bias softmax => partials add exactly.
// ============================================================================
__global__ __launch_bounds__(256, 4)
void attn_kernel(const float* __restrict__ temperature) {
    __shared__ __align__(16) unsigned sK[2][CHUNK * 4];   // 8 KB each
    __shared__ __align__(16) unsigned sVT[2][8 * CPAD];   // 8.3 KB each

    const int h    = blockIdx.y;
    const int s    = blockIdx.z;
    const int tid  = threadIdx.x;
    const int wid  = tid >> 5;
    const int lane = tid & 31;
    const int r = lane >> 2, m = lane & 3;
    const int q0 = blockIdx.x * 128 + wid * 16;

    const float bias = -fabsf(temperature[h]) * 1.4426950408889634f;
    const unsigned ONES = 0x3C003C00u;

    const unsigned* qU = (const unsigned*)g_qh + (size_t)h * HW * 4;
    const unsigned a0q = qU[(q0 + r) * 4 + m];
    const unsigned a1q = qU[(q0 + r + 8) * 4 + m];

    float o0 = 0.f, o1 = 0.f, o2 = 0.f, o3 = 0.f;
    float dd0 = 0.f, dd1 = 0.f, dd2 = 0.f, dd3 = 0.f;

    const uint4*    gK4 = (const uint4*)((const unsigned*)g_kh + (size_t)h * HW * 4);
    const unsigned* gV  = (const unsigned*)g_vt + (size_t)h * 8 * (HW / 2);

    const int ch0 = s * 2;     // 2 chunks of 512 per block

#pragma unroll
    for (int b = 0; b < 2; b++) {
        const int ch = ch0 + b;
#pragma unroll
        for (int i = tid; i < CHUNK; i += 256)
            cp16(&((uint4*)sK[b])[i], &gK4[ch * CHUNK + i]);
#pragma unroll
        for (int i = tid; i < 512; i += 256) {
            const int row = i >> 6, c16 = i & 63;
            cp16((uint4*)(sVT[b] + row * CPAD + c16 * 4),
                 (const uint4*)(gV + row * (HW / 2) + ch * (CHUNK / 2) + c16 * 4));
        }
        CP_COMMIT();
    }

#pragma unroll
    for (int b = 0; b < 2; b++) {
        if (b == 0) { CP_WAIT(1); } else { CP_WAIT(0); }
        __syncthreads();

        const unsigned* bK = sK[b];
        const unsigned* bV = sVT[b];
#pragma unroll 4
        for (int kb = 0; kb < CHUNK; kb += 16) {
            const unsigned kb0 = bK[(kb + r) * 4 + m];
            const unsigned kb1 = bK[(kb + 8 + r) * 4 + m];

            float s0, s1, s2, s3, t0, t1, t2, t3;
            mma_s(s0, s1, s2, s3, a0q, a1q, kb0, bias);
            mma_s(t0, t1, t2, t3, a0q, a1q, kb1, bias);

            const unsigned p0 = ex2h2(packh2(s0, s1));
            const unsigned p1 = ex2h2(packh2(s2, s3));
            const unsigned p2 = ex2h2(packh2(t0, t1));
            const unsigned p3 = ex2h2(packh2(t2, t3));

            const unsigned vb0 = bV[r * CPAD + (kb >> 1) + m];
            const unsigned vb1 = bV[r * CPAD + (kb >> 1) + m + 4];
            mma16(o0, o1, o2, o3, p0, p1, p2, p3, vb0, vb1);
            mma16(dd0, dd1, dd2, dd3, p0, p1, p2, p3, ONES, ONES);
        }
    }

    // transposed partial writes: [s][p][c]
    float* pa = g_pacct + (size_t)s * (HW * 64);
    *(float2*)&pa[(size_t)(q0 + r    ) * 64 + h * 8 + 2 * m] = make_float2(o0, o1);
    *(float2*)&pa[(size_t)(q0 + r + 8) * 64 + h * 8 + 2 * m] = make_float2(o2, o3);
    if (m == 0) {   // dd0/dd2 identical across the quad (B = ones)
        float* pd = g_pden + ((size_t)s * NH + h) * HW;
        pd[q0 + r    ] = dd0;
        pd[q0 + r + 8] = dd2;
    }
}

// ============================================================================
// Kernel 3: fused reduce + output projection on HMMA.
// Block = 256 thr (8 warps), FPIX=32 pixels; grid = 128.
// ============================================================================
__global__ __launch_bounds__(256)
void finish_kernel(const float* __restrict__ wout, float* __restrict__ out) {
    __shared__ unsigned sW[64 * 36];     // f16 pairs [o][36], 9 KB
    __shared__ unsigned sB[FPIX * 36];   // f16 pairs [p][36], 4.5 KB
    __shared__ float sRden[NH * FPIX];   // 1 KB
    const int tid   = threadIdx.x;
    const int pbase = blockIdx.x * FPIX;

#pragma unroll
    for (int i = tid; i < 64 * 32; i += 256) {
        const int o = i >> 5, cp = i & 31;
        const float2 w = *(const float2*)&wout[o * 64 + cp * 2];
        sW[o * 36 + cp] = packh2(w.x, w.y);
    }

    if (tid < NH * (FPIX / 4)) {
        const int h = tid >> 3, g = tid & 7;
        float4 d = make_float4(0.f, 0.f, 0.f, 0.f);
#pragma unroll
        for (int s = 0; s < KS; s++) {
            const float4 v = *(const float4*)&g_pden[((size_t)s * NH + h) * HW + pbase + g * 4];
            d.x += v.x; d.y += v.y; d.z += v.z; d.w += v.w;
        }
        *(float4*)&sRden[h * FPIX + g * 4] =
            make_float4(1.f / d.x, 1.f / d.y, 1.f / d.z, 1.f / d.w);
    }
    __syncthreads();

#pragma unroll
    for (int i = tid; i < FPIX * 16; i += 256) {
        const int p = i >> 4, cg = i & 15;
        float4 a = make_float4(0.f, 0.f, 0.f, 0.f);
#pragma unroll
        for (int s = 0; s < KS; s++) {
            const float4 v = *(const float4*)
                &g_pacct[(size_t)s * (HW * 64) + (size_t)(pbase + p) * 64 + cg * 4];
            a.x += v.x; a.y += v.y; a.z += v.z; a.w += v.w;
        }
        const float rd = sRden[(cg >> 1) * FPIX + p];
        sB[p * 36 + cg * 2]     = packh2(a.x * rd, a.y * rd);
        sB[p * 36 + cg * 2 + 1] = packh2(a.z * rd, a.w * rd);
    }
    __syncthreads();

    const int w    = tid >> 5;
    const int lane = tid & 31;
    const int r = lane >> 2, m4 = lane & 3;
    const int mrow = (w & 3) * 16;
    const int nt0  = (w >> 2) * 2;

    unsigned A[4][4];
#pragma unroll
    for (int k = 0; k < 4; k++) {
        A[k][0] = sW[(mrow + r    ) * 36 + 8 * k + m4];
        A[k][1] = sW[(mrow + r + 8) * 36 + 8 * k + m4];
        A[k][2] = sW[(mrow + r    ) * 36 + 8 * k + m4 + 4];
        A[k][3] = sW[(mrow + r + 8) * 36 + 8 * k + m4 + 4];
    }

#pragma unroll
    for (int nt = nt0; nt < nt0 + 2; nt++) {
        float d0 = 0.f, d1 = 0.f, d2 = 0.f, d3 = 0.f;
#pragma unroll
        for (int k = 0; k < 4; k++) {
            const unsigned b0 = sB[(nt * 8 + r) * 36 + 8 * k + m4];
            const unsigned b1 = sB[(nt * 8 + r) * 36 + 8 * k + m4 + 4];
            mma16(d0, d1, d2, d3, A[k][0], A[k][1], A[k][2], A[k][3], b0, b1);
        }
        const int pcol = pbase + nt * 8 + 2 * m4;
        *(float2*)&out[(size_t)(mrow + r    ) * HW + pcol] = make_float2(d0, d1);
        *(float2*)&out[(size_t)(mrow + r + 8) * HW + pcol] = make_float2(d2, d3);
    }
}

// ============================================================================
extern "C" void kernel_launch(void* const* d_in, const int* in_sizes, int n_in,
                              void* d_out, int out_size) {
    const float* x    = (const float*)d_in[0];
    const float* y    = (const float*)d_in[1];
    const float* wq   = (const float*)d_in[2];
    const float* wkv  = (const float*)d_in[3];
    const float* wout = (const float*)d_in[4];
    const float* temp = (const float*)d_in[5];
    float* out = (float*)d_out;

    prep_kernel<<<dim3(64, 3), 256>>>(x, y, wq, wkv, temp);
    attn_kernel<<<dim3(32, 8, KS), 256>>>(temp);
    finish_kernel<<<128, 256>>>(wout, out);
}